// round 15
// baseline (speedup 1.0000x reference)
#include <cuda_runtime.h>
#include <cuda_fp16.h>
#include <cstdint>

// Problem constants
#define Bsz 512
#define Lsz 256
#define Esz 300
#define EP  304              // padded E (16B-aligned fp16 rows)
#define Hsz 200
#define NCAT 640             // packed vocab-GEMM width: [W1a | W1cT | W1cB | pad]
#define VOC 50000
constexpr long BL  = (long)Bsz * Lsz;      // 131072
constexpr long LL  = (long)Lsz * Lsz;      // 65536
constexpr long BLL = BL * Lsz;             // 33,554,432

// ---------------- device scratch (static, no runtime allocation) -------------
__device__ __half g_embh[(long)VOC * EP];
__device__ __half g_Wcat[EP * NCAT];        // cols 0..199 W1a, 200..399 W1cT, 400..599 W1cB
__device__ __half g_W2a[Hsz * Hsz];
__device__ __half g_W2c[Hsz * Hsz];
__device__ __half g_W1g[2 * Hsz * Hsz];
__device__ float  g_b1acat[NCAT];           // b1a zero-extended to 640
__device__ __half g_vcb[(long)(VOC + 1) * NCAT];  // +1 zero row (index VOC)
__device__ __half g_hvh[(long)VOC * Hsz];   // vocab attend_ff out
__device__ __half g_ph[BLL];                // RAW p = exp(score - Mb), valid rect only
__device__ __half g_thh[2 * BL * Hsz];      // compare hidden
__device__ __half g_vch[Bsz * 2 * Hsz];     // vcat fp16
__device__ float  g_vcatf[Bsz * 2 * Hsz];   // vcat fp32 accumulator
__device__ float    g_scores[BLL];          // zero-init; skipped tiles stay 0
__device__ float    g_mask[2 * BL];
__device__ int      g_tok[2 * BL];          // token id, or VOC (zero row) if masked
__device__ int      g_len12[2 * Bsz];       // [len1 ; len2]
__device__ unsigned g_bmaxu[Bsz];           // encoded per-batch max
__device__ float    g_rsa[BL];              // (j<len2) ? 1/d_alpha_j : 0
__device__ float    g_rsb[BL];              // (i<len1) ? 1/d_beta_i  : 0
__device__ float    g_u[Bsz * Hsz];

// ---------------- PTX helpers ------------------------------------------------
__device__ __forceinline__ void cp16(uint32_t dst, const void* src, bool pred)
{
    int sz = pred ? 16 : 0;                 // sz=0 -> 16B zero-fill
    asm volatile("cp.async.cg.shared.global [%0], [%1], 16, %2;"
                 :: "r"(dst), "l"(src), "r"(sz));
}
__device__ __forceinline__ void cp_commit() { asm volatile("cp.async.commit_group;"); }
template <int N>
__device__ __forceinline__ void cp_wait() { asm volatile("cp.async.wait_group %0;" :: "n"(N)); }

__device__ __forceinline__ void ldsm4(uint32_t* r, uint32_t a)
{
    asm volatile("ldmatrix.sync.aligned.m8n8.x4.shared.b16 {%0,%1,%2,%3}, [%4];"
                 : "=r"(r[0]), "=r"(r[1]), "=r"(r[2]), "=r"(r[3]) : "r"(a));
}
__device__ __forceinline__ void ldsm4t(uint32_t* r, uint32_t a)
{
    asm volatile("ldmatrix.sync.aligned.m8n8.x4.trans.shared.b16 {%0,%1,%2,%3}, [%4];"
                 : "=r"(r[0]), "=r"(r[1]), "=r"(r[2]), "=r"(r[3]) : "r"(a));
}
__device__ __forceinline__ void mma16816(float c[4], const uint32_t a[4], const uint32_t* b)
{
    asm volatile(
        "mma.sync.aligned.m16n8k16.row.col.f32.f16.f16.f32 "
        "{%0,%1,%2,%3}, {%4,%5,%6,%7}, {%8,%9}, {%0,%1,%2,%3};"
        : "+f"(c[0]), "+f"(c[1]), "+f"(c[2]), "+f"(c[3])
        : "r"(a[0]), "r"(a[1]), "r"(a[2]), "r"(a[3]), "r"(b[0]), "r"(b[1]));
}

// ordered-uint encoding of float for atomicMax (monotone)
__device__ __forceinline__ unsigned fenc(float f)
{
    unsigned u = __float_as_uint(f);
    return (u & 0x80000000u) ? ~u : (u | 0x80000000u);
}
__device__ __forceinline__ float fdec(unsigned e)
{
    return (e & 0x80000000u) ? __uint_as_float(e & 0x7FFFFFFFu)
                             : __uint_as_float(~e);
}

// ---------------- 128x128x32 fp16 tensor GEMM, 4-stage cp.async + LDSM -------
// KT = number of 32-wide k-tiles (compile-time -> fully unrolled mainloop).
// C[bz][m,n] = epi( sum_k A(m,k) * B(k,n) ), fp32 accumulate.
// TA: A[m,k]=A[k*lda+m]; TB: B[k,n]=B[n*ldb+k].
// iA (only !TA): source row of A-row m is iA[bz*256+m] (caller passes sA=0).
// iB: source row of B's leading dim (k if !TB, n if TB) is iB[bz*256+row].
//     Index VOC selects the all-zero vcb row (masked positions).
// Masked-block skip: skip iff rskip OR cskip.
// klimP: per-batch K limit: k-tiles with kt*32 >= klimP[bz] are all-zero
//   (zero-B rows) -> skip LDSM+MMA only (loads stay uniform).
// epilogue: rsPre ? (acc*rs then +Cin+bias, relu)
//                 : (+Cin+bias, relu, *rs);   relu iff n < nrelu;
//           vacc: fused column-sum -> atomicAdd, no C store;
//           bmaxu: per-batch atomicMax of raw acc (exact tiles only).
template <int KT, bool TA, bool TB, bool OUTH>
__global__ __launch_bounds__(256, 2)
void gemm_h(const __half* __restrict__ A, long sA, int lda, const int* __restrict__ iA,
            const __half* __restrict__ Bw, long sB, int ldb, const int* __restrict__ iB,
            const float* __restrict__ bias,
            const float* __restrict__ rs, int sRS, int rsPre,
            const __half* __restrict__ Cin, const int* __restrict__ iC, int ldcin,
            void* __restrict__ Cv, long sC, int ldc,
            int M, int N, int K, int nrelu,
            unsigned* bmaxu, float* vacc,
            const int* __restrict__ lenRow, const int* __restrict__ lenCol,
            const int* __restrict__ klimP)
{
    constexpr int A_SZ = TA ? 32 * 136 : 128 * 40;   // halfs per stage
    constexpr int B_SZ = TB ? 128 * 40 : 32 * 136;
    extern __shared__ __half smem_[];
    __half* Asm = smem_;                  // 4 stages of A
    __half* Bsm = smem_ + 4 * A_SZ;       // 4 stages of B

    int bz = blockIdx.z;
    int m0 = blockIdx.y * 128, n0 = blockIdx.x * 128;

    // ---- masked-block skip (OR semantics)
    if (lenRow) {
        bool rskip = (m0 & 255) >= lenRow[bz + (m0 >> 8)];
        bool cskip = lenCol && ((n0 & 255) >= lenCol[bz + (n0 >> 8)]);
        if (rskip || cskip) return;
    }
    int kl = klimP ? ((klimP[bz] + 31) >> 5) : KT;   // active k-tiles

    const __half* Ab = A + (long)bz * sA;
    const __half* Bb = Bw + (long)bz * sB;
    int tid = threadIdx.x;
    int wid = tid >> 5, lane = tid & 31;
    int wm = wid >> 2, wn = wid & 3;
    int g = lane >> 2, tig = lane & 3;

    uint32_t abase = (uint32_t)__cvta_generic_to_shared(Asm);
    uint32_t bbase = (uint32_t)__cvta_generic_to_shared(Bsm);

    float c[4][4][4];
#pragma unroll
    for (int i = 0; i < 4; i++)
#pragma unroll
        for (int j = 0; j < 4; j++)
#pragma unroll
            for (int q = 0; q < 4; q++) c[i][j][q] = 0.f;

    auto load_stage = [&](int st, int k0) {
#pragma unroll
        for (int it = 0; it < 2; it++) {
            int id = tid + it * 256;
            if (!TA) {
                int row = id >> 2, c8 = (id & 3) * 8;
                bool p = (m0 + row < M) && (k0 + c8 < K);
                int rg = iA ? (p ? iA[bz * 256 + m0 + row] : 0) : (m0 + row);
                cp16(abase + (uint32_t)(st * A_SZ + row * 40 + c8) * 2,
                     Ab + (long)rg * lda + (k0 + c8), p);
            } else {
                int kr = id >> 4, c8 = (id & 15) * 8;
                bool p = (k0 + kr < K) && (m0 + c8 < M);
                cp16(abase + (uint32_t)(st * A_SZ + kr * 136 + c8) * 2,
                     Ab + (long)(k0 + kr) * lda + (m0 + c8), p);
            }
            if (!TB) {
                int kr = id >> 4, c8 = (id & 15) * 8;
                bool p = (k0 + kr < K) && (n0 + c8 < N);
                int rg = iB ? ((k0 + kr < K) ? iB[bz * 256 + k0 + kr] : 0) : (k0 + kr);
                cp16(bbase + (uint32_t)(st * B_SZ + kr * 136 + c8) * 2,
                     Bb + (long)rg * ldb + (n0 + c8), p);
            } else {
                int row = id >> 2, c8 = (id & 3) * 8;
                bool p = (n0 + row < N) && (k0 + c8 < K);
                int rg = iB ? ((n0 + row < N) ? iB[bz * 256 + n0 + row] : 0) : (n0 + row);
                cp16(bbase + (uint32_t)(st * B_SZ + row * 40 + c8) * 2,
                     Bb + (long)rg * ldb + (k0 + c8), p);
            }
        }
        cp_commit();
    };

    load_stage(0, 0);
    if (KT > 1) load_stage(1, 32);
    if (KT > 2) load_stage(2, 64);

#pragma unroll
    for (int kt = 0; kt < KT; kt++) {
        if (kt < KT - 2)       cp_wait<2>();
        else if (kt == KT - 2) cp_wait<1>();
        else                   cp_wait<0>();
        __syncthreads();    // single barrier: stage (kt+3)&3 == (kt-1)&3 is free
        if (kt < kl) {      // block-uniform: skip dead k-tiles' compute only
            int st = kt & 3;
            uint32_t ab2 = abase + (uint32_t)(st * A_SZ) * 2;
            uint32_t bb2 = bbase + (uint32_t)(st * B_SZ) * 2;

#pragma unroll
            for (int s2 = 0; s2 < 2; s2++) {
                int ks = s2 * 16;
                uint32_t af[4][4], bq[2][4];
#pragma unroll
                for (int mt = 0; mt < 4; mt++) {
                    if (!TA) {
                        int m = wm * 64 + mt * 16 + (lane & 15);
                        int kc = ks + ((lane >> 4) << 3);
                        ldsm4(af[mt], ab2 + (uint32_t)(m * 40 + kc) * 2);
                    } else {
                        int kr = ks + (lane & 7) + ((lane >> 4) << 3);
                        int mc = wm * 64 + mt * 16 + (((lane >> 3) & 1) << 3);
                        ldsm4t(af[mt], ab2 + (uint32_t)(kr * 136 + mc) * 2);
                    }
                }
#pragma unroll
                for (int np = 0; np < 2; np++) {
                    if (TB) {
                        int n = wn * 32 + np * 16 + ((lane >> 4) << 3) + (lane & 7);
                        int kc = ks + (((lane >> 3) & 1) << 3);
                        ldsm4(bq[np], bb2 + (uint32_t)(n * 40 + kc) * 2);
                    } else {
                        int kr = ks + (lane & 7) + (((lane >> 3) & 1) << 3);
                        int nc = wn * 32 + np * 16 + (((lane >> 4) & 1) << 3);
                        ldsm4t(bq[np], bb2 + (uint32_t)(kr * 136 + nc) * 2);
                    }
                }
#pragma unroll
                for (int mt = 0; mt < 4; mt++)
#pragma unroll
                    for (int nt = 0; nt < 4; nt++)
                        mma16816(c[mt][nt], af[mt], &bq[nt >> 1][(nt & 1) * 2]);
            }
        }
        if (kt + 3 < KT) load_stage((kt + 3) & 3, (kt + 3) * 32);
    }

    // ---- fused column-sum epilogue (compare L2): no C store
    if (vacc) {
        int b2v = m0 >> 8;   // 128-row blocks never straddle a 256-row segment
        int voff = (b2v < Bsz) ? b2v * (2 * Hsz) : (b2v - Bsz) * (2 * Hsz) + Hsz;
#pragma unroll
        for (int nt = 0; nt < 4; nt++) {
            int n = n0 + wn * 32 + nt * 8 + tig * 2;
            float s0 = 0.f, s1 = 0.f;
            if (n < N) {
#pragma unroll
                for (int mt = 0; mt < 4; mt++)
#pragma unroll
                    for (int r = 0; r < 2; r++) {
                        int m = m0 + wm * 64 + mt * 16 + g + r * 8;
                        float rsv = rs ? rs[(long)bz * sRS + m] : 1.f;
                        float v0 = c[mt][nt][r * 2 + 0];
                        float v1 = c[mt][nt][r * 2 + 1];
                        if (bias) { v0 += bias[n]; v1 += bias[n + 1]; }
                        if (n < nrelu) { v0 = fmaxf(v0, 0.f); v1 = fmaxf(v1, 0.f); }
                        s0 += v0 * rsv; s1 += v1 * rsv;
                    }
            }
            s0 += __shfl_down_sync(~0u, s0, 16);
            s0 += __shfl_down_sync(~0u, s0, 8);
            s0 += __shfl_down_sync(~0u, s0, 4);
            s1 += __shfl_down_sync(~0u, s1, 16);
            s1 += __shfl_down_sync(~0u, s1, 8);
            s1 += __shfl_down_sync(~0u, s1, 4);
            if (g == 0 && n < N) {
                atomicAdd(&vacc[voff + n], s0);
                atomicAdd(&vacc[voff + n + 1], s1);
            }
        }
        return;
    }

    __half* Ch = (__half*)Cv + (long)bz * sC;
    float*  Cf = (float*)Cv + (long)bz * sC;
#pragma unroll
    for (int mt = 0; mt < 4; mt++) {
#pragma unroll
        for (int r = 0; r < 2; r++) {
            int m = m0 + wm * 64 + mt * 16 + g + r * 8;
            if (m >= M) continue;
            float rsv = rs ? rs[(long)bz * sRS + m] : 1.f;
            int crow = 0;
            if (Cin) crow = iC ? iC[bz * 256 + m] : m;
#pragma unroll
            for (int nt = 0; nt < 4; nt++) {
                int n = n0 + wn * 32 + nt * 8 + tig * 2;
                if (n < N) {
                    float v0 = c[mt][nt][r * 2 + 0];
                    float v1 = c[mt][nt][r * 2 + 1];
                    if (rsPre) { v0 *= rsv; v1 *= rsv; }
                    if (Cin) {
                        v0 += __half2float(Cin[(long)crow * ldcin + n]);
                        v1 += __half2float(Cin[(long)crow * ldcin + n + 1]);
                    }
                    if (bias) { v0 += bias[n]; v1 += bias[n + 1]; }
                    if (n < nrelu) { v0 = fmaxf(v0, 0.f); v1 = fmaxf(v1, 0.f); }
                    if (!rsPre) { v0 *= rsv; v1 *= rsv; }
                    if (OUTH)
                        *(__half2*)(Ch + (long)m * ldc + n) = __floats2half2_rn(v0, v1);
                    else {
                        Cf[(long)m * ldc + n] = v0;
                        Cf[(long)m * ldc + n + 1] = v1;
                    }
                }
            }
        }
    }

    if (bmaxu) {   // per-batch max of this block's outputs (exact tiles only)
        float mx = -1e30f;
#pragma unroll
        for (int mt = 0; mt < 4; mt++)
#pragma unroll
            for (int nt = 0; nt < 4; nt++)
#pragma unroll
                for (int q = 0; q < 4; q++) mx = fmaxf(mx, c[mt][nt][q]);
#pragma unroll
        for (int o = 16; o; o >>= 1) mx = fmaxf(mx, __shfl_xor_sync(~0u, mx, o));
        if (lane == 0) atomicMax(&bmaxu[bz], fenc(mx));
    }
}

// dynamic smem bytes per instantiation (4 stages)
constexpr int smem_bytes(bool TA, bool TB)
{
    int a = TA ? 32 * 136 : 128 * 40;
    int b = TB ? 128 * 40 : 32 * 136;
    return 4 * (a + b) * 2;
}

// ---------------- helper kernels ---------------------------------------------
__global__ void conv2h_k(const float* __restrict__ src, __half* __restrict__ dst,
                         int rows, int cols, int srcR, int srcC)
{
    long idx = (long)blockIdx.x * blockDim.x + threadIdx.x;
    if (idx >= (long)rows * cols) return;
    int r = (int)(idx / cols), c = (int)(idx % cols);
    float v = (r < srcR && c < srcC) ? src[(long)r * srcC + c] : 0.f;
    dst[idx] = __float2half_rn(v);
}

// all weight conversions in ONE kernel (Wcat packing + W2a/W2c/W1g + biascat)
__global__ void convw_k(const float* __restrict__ W1a, const float* __restrict__ W1c,
                        const float* __restrict__ W2a, const float* __restrict__ W2c,
                        const float* __restrict__ W1g, const float* __restrict__ b1a)
{
    long idx = (long)blockIdx.x * blockDim.x + threadIdx.x;
    const long NW = (long)EP * NCAT;
    if (idx < NW) {
        int r = (int)(idx / NCAT), cc = (int)(idx % NCAT);
        float v = 0.f;
        if (r < Esz) {
            if (cc < 200)      v = W1a[(long)r * Hsz + cc];
            else if (cc < 400) v = W1c[(long)r * Hsz + (cc - 200)];
            else if (cc < 600) v = W1c[(long)(Esz + r) * Hsz + (cc - 400)];
        }
        g_Wcat[idx] = __float2half_rn(v);
        return;
    }
    idx -= NW;
    if (idx < Hsz * Hsz) { g_W2a[idx] = __float2half_rn(W2a[idx]); return; }
    idx -= Hsz * Hsz;
    if (idx < Hsz * Hsz) { g_W2c[idx] = __float2half_rn(W2c[idx]); return; }
    idx -= Hsz * Hsz;
    if (idx < 2 * Hsz * Hsz) { g_W1g[idx] = __float2half_rn(W1g[idx]); return; }
    idx -= 2 * Hsz * Hsz;
    if (idx < NCAT) { g_b1acat[idx] = (idx < Hsz) ? b1a[idx] : 0.f; return; }
}

// masks + VOC-masked token indices + lens + bmax init + vcat accumulator zero
__global__ void mask_k(const int* __restrict__ s1, const int* __restrict__ s2,
                       const int* __restrict__ len1, const int* __restrict__ len2)
{
    long idx = (long)blockIdx.x * blockDim.x + threadIdx.x;
    if (idx >= 2 * BL) return;
    int seq = (int)(idx / BL);
    long r = idx % BL;
    int b = (int)(r / Lsz), l = (int)(r % Lsz);
    int len = seq ? len2[b] : len1[b];
    g_mask[idx] = (l < len) ? 1.f : 0.f;
    g_tok[idx] = (l < len) ? (seq ? s2[r] : s1[r]) : VOC;   // VOC = zero row
    if (idx < Bsz) g_bmaxu[idx] = 0u;
    if (idx < 2 * Bsz) g_len12[idx] = (idx < Bsz) ? len1[idx] : len2[idx - Bsz];
    if (idx < Bsz * 2 * Hsz) g_vcatf[idx] = 0.f;
}

// Single-pass softmax over the VALID rectangle only:
// p = exp(score - Mb) for (i < len1, j < len2) -> g_ph (fp16);
// colsum(p) -> rsa = 1/d (j<len2 else 0); rowsum(p) -> rsb = 1/d (i<len1 else 0).
// All p outside the rectangle is neutralized downstream by zero vcb rows /
// masks; unwritten g_ph entries are 0 (zero-init, deterministic).
__global__ void sums_k()
{
    __shared__ float rowacc[256];
    __shared__ float colsm[1024];
    int b = blockIdx.x;
    int tid = threadIdx.x;
    int j = tid & 255, s = tid >> 8, lane = tid & 31;
    int l1 = g_len12[b], l2 = g_len12[Bsz + b];
    if (tid < 256) rowacc[tid] = 0.f;
    __syncthreads();

    long base = (long)b * LL;
    float Mb  = fdec(g_bmaxu[b]);
    float da = 0.f;
    bool wact = (j & ~31) < l2;          // warp-uniform (32 consecutive j per warp)
    if (wact) {
        bool act = (j < l2);
        for (int i = s; i < l1; i += 4) {   // stride-4 interleave across slices
            long idx = base + (long)i * Lsz + j;
            float p = act ? __expf(g_scores[idx] - Mb) : 0.f;
            da += p;
            if (act) g_ph[idx] = __float2half_rn(p);
            float w = p;
#pragma unroll
            for (int o = 16; o; o >>= 1) w += __shfl_xor_sync(~0u, w, o);
            if (lane == 0) atomicAdd(&rowacc[i], w);
        }
    }
    colsm[tid] = da;
    __syncthreads();
    if (s == 0) {
        float d = colsm[j] + colsm[j + 256] + colsm[j + 512] + colsm[j + 768];
        g_rsa[(long)b * Lsz + j] = (j < l2) ? (1.f / d) : 0.f;
    }
    if (tid < 256)
        g_rsb[(long)b * Lsz + tid] = (tid < l1) ? (1.f / rowacc[tid]) : 0.f;
}

__global__ void vconv_k()    // fp32 vcat accumulator -> fp16
{
    int idx = blockIdx.x * blockDim.x + threadIdx.x;
    if (idx < Bsz * 2 * Hsz) g_vch[idx] = __float2half_rn(g_vcatf[idx]);
}

__global__ void final_k(const float* __restrict__ W2g,
                        const float* __restrict__ b2g, float* __restrict__ out)
{
    int b = blockIdx.x;
    int o = threadIdx.x >> 5;
    int lane = threadIdx.x & 31;
    const float* u = g_u + (long)b * Hsz;
    float s = 0.f;
    for (int h = lane; h < Hsz; h += 32) s += u[h] * W2g[h * 2 + o];
#pragma unroll
    for (int off = 16; off; off >>= 1) s += __shfl_xor_sync(~0u, s, off);
    if (lane == 0) out[b * 2 + o] = s + b2g[o];
}

// ---------------- launch -----------------------------------------------------
extern "C" void kernel_launch(void* const* d_in, const int* in_sizes, int n_in,
                              void* d_out, int out_size)
{
    const float* emb = (const float*)d_in[0];
    const float* W1a = (const float*)d_in[1];
    const float* b1a = (const float*)d_in[2];
    const float* W2a = (const float*)d_in[3];
    const float* b2a = (const float*)d_in[4];
    const float* W1c = (const float*)d_in[5];
    const float* b1c = (const float*)d_in[6];
    const float* W2c = (const float*)d_in[7];
    const float* b2c = (const float*)d_in[8];
    const float* W1g = (const float*)d_in[9];
    const float* b1g = (const float*)d_in[10];
    const float* W2g = (const float*)d_in[11];
    const float* b2g = (const float*)d_in[12];
    const int* s1   = (const int*)d_in[13];
    const int* s2   = (const int*)d_in[14];
    const int* len1 = (const int*)d_in[15];
    const int* len2 = (const int*)d_in[16];
    float* out = (float*)d_out;

    __half *pembh, *pWcat, *pW2a, *pW2c, *pW1g, *pvcb, *phvh;
    __half *pph, *pthh, *pvch;
    float *pmask, *pu, *psc, *pb1acat, *pvcatf, *prsa, *prsb;
    int *ptok, *plen;
    unsigned *pbmx;
    cudaGetSymbolAddress((void**)&pembh,  g_embh);
    cudaGetSymbolAddress((void**)&pWcat,  g_Wcat);
    cudaGetSymbolAddress((void**)&pW2a,   g_W2a);
    cudaGetSymbolAddress((void**)&pW2c,   g_W2c);
    cudaGetSymbolAddress((void**)&pW1g,   g_W1g);
    cudaGetSymbolAddress((void**)&pvcb,   g_vcb);
    cudaGetSymbolAddress((void**)&phvh,   g_hvh);
    cudaGetSymbolAddress((void**)&pph,    g_ph);
    cudaGetSymbolAddress((void**)&pthh,   g_thh);
    cudaGetSymbolAddress((void**)&pvch,   g_vch);
    cudaGetSymbolAddress((void**)&pmask,  g_mask);
    cudaGetSymbolAddress((void**)&pu,     g_u);
    cudaGetSymbolAddress((void**)&psc,    g_scores);
    cudaGetSymbolAddress((void**)&pb1acat,g_b1acat);
    cudaGetSymbolAddress((void**)&pvcatf, g_vcatf);
    cudaGetSymbolAddress((void**)&prsa,   g_rsa);
    cudaGetSymbolAddress((void**)&prsb,   g_rsb);
    cudaGetSymbolAddress((void**)&ptok,   g_tok);
    cudaGetSymbolAddress((void**)&plen,   g_len12);
    cudaGetSymbolAddress((void**)&pbmx,   g_bmaxu);

    const int M2 = (int)(2 * BL);          // 262144
    const unsigned MV = (VOC + 127) / 128; // 391
    const int RALL = 1 << 30;              // relu on all columns
    auto cdiv = [](long n, long d) { return (unsigned)((n + d - 1) / d); };

    // KT per call site: EP=304 -> 10, K=200 -> 7, K=256 -> 8, K=400 -> 13
    constexpr int SM_FF = smem_bytes(false, false);   // 75776
    constexpr int SM_FT = smem_bytes(false, true);    // 81920
    constexpr int SM_TF = smem_bytes(true,  false);   // 75776
    cudaFuncSetAttribute((const void*)gemm_h<10,false,false,true>,
                         cudaFuncAttributeMaxDynamicSharedMemorySize, SM_FF);
    cudaFuncSetAttribute((const void*)gemm_h<7,false,false,true>,
                         cudaFuncAttributeMaxDynamicSharedMemorySize, SM_FF);
    cudaFuncSetAttribute((const void*)gemm_h<7,false,true,false>,
                         cudaFuncAttributeMaxDynamicSharedMemorySize, SM_FT);
    cudaFuncSetAttribute((const void*)gemm_h<8,false,false,true>,
                         cudaFuncAttributeMaxDynamicSharedMemorySize, SM_FF);
    cudaFuncSetAttribute((const void*)gemm_h<8,true,false,true>,
                         cudaFuncAttributeMaxDynamicSharedMemorySize, SM_TF);
    cudaFuncSetAttribute((const void*)gemm_h<13,false,false,false>,
                         cudaFuncAttributeMaxDynamicSharedMemorySize, SM_FF);

    // 1. emb -> fp16 (padded)
    conv2h_k<<<cdiv((long)VOC * EP, 256), 256>>>(emb, pembh, VOC, EP, VOC, Esz);
    // 2. all weights in one kernel
    long wtot = (long)EP * NCAT + 2 * Hsz * Hsz + 2 * Hsz * Hsz + NCAT;
    convw_k<<<cdiv(wtot, 256), 256>>>(W1a, W1c, W2a, W2c, W1g, b1a);
    // 3. masks + VOC-masked tok + lens + bmax + vcat zero
    mask_k<<<cdiv(2 * BL, 256), 256>>>(s1, s2, len1, len2);

    // 4. fused vocab GEMM: [attendL1(relu,b1a) | e@W1cT | e@W1cB]  (N=640, K=EP)
    //    (row VOC of g_vcb stays zero: masked-token B rows / Cin gathers)
    gemm_h<10,false,false,true><<<dim3(5, MV, 1), 256, SM_FF>>>(
        pembh, 0, EP, nullptr, pWcat, 0, NCAT, nullptr, pb1acat, nullptr, 0, 0,
        nullptr, nullptr, 0, pvcb, 0, NCAT, VOC, NCAT, EP, Hsz,
        nullptr, nullptr, nullptr, nullptr, nullptr);
    // 5. attend L2: hv = relu(vcb[:, :200] @ W2a + b2a)   (K=200)
    gemm_h<7,false,false,true><<<dim3(2, MV, 1), 256, SM_FF>>>(
        pvcb, 0, NCAT, nullptr, pW2a, 0, Hsz, nullptr, b2a, nullptr, 0, 0,
        nullptr, nullptr, 0, phvh, 0, Hsz, VOC, Hsz, Hsz, RALL,
        nullptr, nullptr, nullptr, nullptr, nullptr);

    // 6. scores[b] = hv[s1] @ hv[s2]^T (K=200; batch-max; OR-skip masked tiles)
    gemm_h<7,false,true,false><<<dim3(2, 2, Bsz), 256, SM_FT>>>(
        phvh, 0, Hsz, s1, phvh, 0, Hsz, s2, nullptr, nullptr, 0, 0,
        nullptr, nullptr, 0, psc, LL, Lsz, Lsz, Lsz, Hsz, 0,
        pbmx, nullptr, plen, plen + Bsz, nullptr);

    // 7. single-pass softmax over valid rectangle -> fp16 p + rsa/rsb
    sums_k<<<Bsz, 1024>>>();

    // 8. compare hidden: th1[i] = relu(rsb_i*(p@cv2z[tok2]) + cvz[tok1] + b1c)
    //    masked j handled by zero vcb rows (tok2=VOC); k-tiles beyond len2 skipped
    gemm_h<8,false,false,true><<<dim3(2, 2, Bsz), 256, SM_FF>>>(
        pph, LL, Lsz, nullptr, pvcb + 400, 0, NCAT, ptok + BL, b1c, prsb, Lsz, 1,
        pvcb + 200, ptok, NCAT, pthh, (long)Lsz * Hsz, Hsz,
        Lsz, Hsz, Lsz, RALL, nullptr, nullptr, plen, nullptr, plen + Bsz);
    //    th2[j] = relu(rsa_j*(p^T@cv2z[tok1]) + cvz[tok2] + b1c)
    gemm_h<8,true,false,true><<<dim3(2, 2, Bsz), 256, SM_TF>>>(
        pph, LL, Lsz, nullptr, pvcb + 400, 0, NCAT, ptok, b1c, prsa, Lsz, 1,
        pvcb + 200, ptok + BL, NCAT, pthh + BL * Hsz, (long)Lsz * Hsz, Hsz,
        Lsz, Hsz, Lsz, RALL, nullptr, nullptr, plen + Bsz, nullptr, plen);

    // 9. compare L2 with fused masked column-sum (K=200; skip fully-masked blocks)
    gemm_h<7,false,false,true><<<dim3(2, M2 / 128, 1), 256, SM_FF>>>(
        pthh, 0, Hsz, nullptr, pW2c, 0, Hsz, nullptr, b2c, pmask, 0, 0,
        nullptr, nullptr, 0, nullptr, 0, Hsz, M2, Hsz, Hsz, RALL,
        nullptr, pvcatf, plen, nullptr, nullptr);

    // 10. vcat fp32 -> fp16 ; aggregate head (K=400)
    vconv_k<<<cdiv(Bsz * 2 * Hsz, 256), 256>>>();
    gemm_h<13,false,false,false><<<dim3(2, 4, 1), 256, SM_FF>>>(
        pvch, 0, 2 * Hsz, nullptr, pW1g, 0, Hsz, nullptr, b1g, nullptr, 0, 0,
        nullptr, nullptr, 0, pu, 0, Hsz, Bsz, Hsz, 2 * Hsz, RALL,
        nullptr, nullptr, nullptr, nullptr, nullptr);
    final_k<<<Bsz, 64>>>(W2g, b2g, out);
}

// round 16
// speedup vs baseline: 1.2392x; 1.2392x over previous
#include <cuda_runtime.h>
#include <cuda_fp16.h>
#include <cstdint>

// Problem constants
#define Bsz 512
#define Lsz 256
#define Esz 300
#define EP  304              // padded E (16B-aligned fp16 rows)
#define Hsz 200
#define NCAT 640             // packed vocab-GEMM width: [W1a | W1cT | W1cB | pad]
#define VOC 50000
constexpr long BL  = (long)Bsz * Lsz;      // 131072
constexpr long LL  = (long)Lsz * Lsz;      // 65536
constexpr long BLL = BL * Lsz;             // 33,554,432

// ---------------- device scratch (static, no runtime allocation) -------------
__device__ __half g_embh[(long)VOC * EP];
__device__ __half g_Wcat[EP * NCAT];        // cols 0..199 W1a, 200..399 W1cT, 400..599 W1cB
__device__ __half g_W2a[Hsz * Hsz];
__device__ __half g_W2c[Hsz * Hsz];
__device__ __half g_W1g[2 * Hsz * Hsz];
__device__ float  g_b1acat[NCAT];           // b1a zero-extended to 640
__device__ __half g_vcb[(long)VOC * NCAT];  // vocab: [attendL1relu | e@W1cT | e@W1cB]
__device__ __half g_hvh[(long)VOC * Hsz];   // vocab attend_ff out
__device__ __half g_eanh[BLL];              // RAW q = p*mask1[i]   (fp16)
__device__ __half g_ebnh[BLL];              // RAW w = p*mask2[j]   (fp16)
__device__ __half g_thh[2 * BL * Hsz];      // compare hidden
__device__ __half g_vch[Bsz * 2 * Hsz];     // vcat fp16
__device__ float  g_vcatf[Bsz * 2 * Hsz];   // vcat fp32 accumulator
__device__ float    g_scores[BLL];          // zero-init; skipped tiles stay 0
__device__ float    g_mask[2 * BL];
__device__ int      g_tok[2 * BL];
__device__ int      g_len12[2 * Bsz];       // [len1 ; len2]
__device__ unsigned g_bmaxu[Bsz];           // encoded per-batch max
__device__ float    g_rsa[BL];              // mask2[j] / d_alpha_j
__device__ float    g_rsb[BL];              // mask1[i] / d_beta_i
__device__ float    g_u[Bsz * Hsz];

// ---------------- PTX helpers ------------------------------------------------
__device__ __forceinline__ void cp16(uint32_t dst, const void* src, bool pred)
{
    int sz = pred ? 16 : 0;                 // sz=0 -> 16B zero-fill
    asm volatile("cp.async.cg.shared.global [%0], [%1], 16, %2;"
                 :: "r"(dst), "l"(src), "r"(sz));
}
__device__ __forceinline__ void cp_commit() { asm volatile("cp.async.commit_group;"); }
template <int N>
__device__ __forceinline__ void cp_wait() { asm volatile("cp.async.wait_group %0;" :: "n"(N)); }

__device__ __forceinline__ void ldsm4(uint32_t* r, uint32_t a)
{
    asm volatile("ldmatrix.sync.aligned.m8n8.x4.shared.b16 {%0,%1,%2,%3}, [%4];"
                 : "=r"(r[0]), "=r"(r[1]), "=r"(r[2]), "=r"(r[3]) : "r"(a));
}
__device__ __forceinline__ void ldsm4t(uint32_t* r, uint32_t a)
{
    asm volatile("ldmatrix.sync.aligned.m8n8.x4.trans.shared.b16 {%0,%1,%2,%3}, [%4];"
                 : "=r"(r[0]), "=r"(r[1]), "=r"(r[2]), "=r"(r[3]) : "r"(a));
}
__device__ __forceinline__ void mma16816(float c[4], const uint32_t a[4], const uint32_t* b)
{
    asm volatile(
        "mma.sync.aligned.m16n8k16.row.col.f32.f16.f16.f32 "
        "{%0,%1,%2,%3}, {%4,%5,%6,%7}, {%8,%9}, {%0,%1,%2,%3};"
        : "+f"(c[0]), "+f"(c[1]), "+f"(c[2]), "+f"(c[3])
        : "r"(a[0]), "r"(a[1]), "r"(a[2]), "r"(a[3]), "r"(b[0]), "r"(b[1]));
}

// ordered-uint encoding of float for atomicMax (monotone)
__device__ __forceinline__ unsigned fenc(float f)
{
    unsigned u = __float_as_uint(f);
    return (u & 0x80000000u) ? ~u : (u | 0x80000000u);
}
__device__ __forceinline__ float fdec(unsigned e)
{
    return (e & 0x80000000u) ? __uint_as_float(e & 0x7FFFFFFFu)
                             : __uint_as_float(~e);
}

// ---------------- 128x128x32 fp16 tensor GEMM, 4-stage cp.async + LDSM -------
// KT = number of 32-wide k-tiles (compile-time -> fully unrolled mainloop).
// C[bz][m,n] = epi( sum_k A(m,k) * B(k,n) ), fp32 accumulate.
// TA: A[m,k]=A[k*lda+m]; TB: B[k,n]=B[n*ldb+k].
// iA (only !TA): source row of A-row m is iA[bz*256+m] (caller passes sA=0).
// iB: source row of B's leading dim (k if !TB, n if TB) is iB[bz*256+row].
// Masked-block skip: skip iff rskip OR cskip (each consumer multiplies the
//   skipped output region by a zero mask; scores buffer stays 0 there).
// klimP: per-batch K limit (elements): k-tiles with kt*32 >= klimP[bz] carry
//   all-zero A columns -> skip LDSM+MMA only (loads stay uniform).
// epilogue: rsPre ? (acc*rs then +Cin+bias, relu)
//                 : (+Cin+bias, relu, *rs);   relu iff n < nrelu;
//           vacc: fused column-sum -> atomicAdd, no C store;
//           bmaxu: per-batch atomicMax of raw acc (exact tiles only).
template <int KT, bool TA, bool TB, bool OUTH>
__global__ __launch_bounds__(256, 2)
void gemm_h(const __half* __restrict__ A, long sA, int lda, const int* __restrict__ iA,
            const __half* __restrict__ Bw, long sB, int ldb, const int* __restrict__ iB,
            const float* __restrict__ bias,
            const float* __restrict__ rs, int sRS, int rsPre,
            const __half* __restrict__ Cin, const int* __restrict__ iC, int ldcin,
            void* __restrict__ Cv, long sC, int ldc,
            int M, int N, int K, int nrelu,
            unsigned* bmaxu, float* vacc,
            const int* __restrict__ lenRow, const int* __restrict__ lenCol,
            const int* __restrict__ klimP)
{
    constexpr int A_SZ = TA ? 32 * 136 : 128 * 40;   // halfs per stage
    constexpr int B_SZ = TB ? 128 * 40 : 32 * 136;
    extern __shared__ __half smem_[];
    __half* Asm = smem_;                  // 4 stages of A
    __half* Bsm = smem_ + 4 * A_SZ;       // 4 stages of B

    int bz = blockIdx.z;
    int m0 = blockIdx.y * 128, n0 = blockIdx.x * 128;

    // ---- masked-block skip (OR semantics)
    if (lenRow) {
        bool rskip = (m0 & 255) >= lenRow[bz + (m0 >> 8)];
        bool cskip = lenCol && ((n0 & 255) >= lenCol[bz + (n0 >> 8)]);
        if (rskip || cskip) return;
    }
    int kl = klimP ? ((klimP[bz] + 31) >> 5) : KT;   // active k-tiles

    const __half* Ab = A + (long)bz * sA;
    const __half* Bb = Bw + (long)bz * sB;
    int tid = threadIdx.x;
    int wid = tid >> 5, lane = tid & 31;
    int wm = wid >> 2, wn = wid & 3;
    int g = lane >> 2, tig = lane & 3;

    uint32_t abase = (uint32_t)__cvta_generic_to_shared(Asm);
    uint32_t bbase = (uint32_t)__cvta_generic_to_shared(Bsm);

    float c[4][4][4];
#pragma unroll
    for (int i = 0; i < 4; i++)
#pragma unroll
        for (int j = 0; j < 4; j++)
#pragma unroll
            for (int q = 0; q < 4; q++) c[i][j][q] = 0.f;

    auto load_stage = [&](int st, int k0) {
#pragma unroll
        for (int it = 0; it < 2; it++) {
            int id = tid + it * 256;
            if (!TA) {
                int row = id >> 2, c8 = (id & 3) * 8;
                bool p = (m0 + row < M) && (k0 + c8 < K);
                int rg = iA ? (p ? iA[bz * 256 + m0 + row] : 0) : (m0 + row);
                cp16(abase + (uint32_t)(st * A_SZ + row * 40 + c8) * 2,
                     Ab + (long)rg * lda + (k0 + c8), p);
            } else {
                int kr = id >> 4, c8 = (id & 15) * 8;
                bool p = (k0 + kr < K) && (m0 + c8 < M);
                cp16(abase + (uint32_t)(st * A_SZ + kr * 136 + c8) * 2,
                     Ab + (long)(k0 + kr) * lda + (m0 + c8), p);
            }
            if (!TB) {
                int kr = id >> 4, c8 = (id & 15) * 8;
                bool p = (k0 + kr < K) && (n0 + c8 < N);
                int rg = iB ? ((k0 + kr < K) ? iB[bz * 256 + k0 + kr] : 0) : (k0 + kr);
                cp16(bbase + (uint32_t)(st * B_SZ + kr * 136 + c8) * 2,
                     Bb + (long)rg * ldb + (n0 + c8), p);
            } else {
                int row = id >> 2, c8 = (id & 3) * 8;
                bool p = (n0 + row < N) && (k0 + c8 < K);
                int rg = iB ? ((n0 + row < N) ? iB[bz * 256 + n0 + row] : 0) : (n0 + row);
                cp16(bbase + (uint32_t)(st * B_SZ + row * 40 + c8) * 2,
                     Bb + (long)rg * ldb + (k0 + c8), p);
            }
        }
        cp_commit();
    };

    load_stage(0, 0);
    if (KT > 1) load_stage(1, 32);
    if (KT > 2) load_stage(2, 64);

#pragma unroll
    for (int kt = 0; kt < KT; kt++) {
        if (kt < KT - 2)       cp_wait<2>();
        else if (kt == KT - 2) cp_wait<1>();
        else                   cp_wait<0>();
        __syncthreads();    // single barrier: stage (kt+3)&3 == (kt-1)&3 is free
        if (kt < kl) {      // block-uniform: skip dead k-tiles' compute only
            int st = kt & 3;
            uint32_t ab2 = abase + (uint32_t)(st * A_SZ) * 2;
            uint32_t bb2 = bbase + (uint32_t)(st * B_SZ) * 2;

#pragma unroll
            for (int s2 = 0; s2 < 2; s2++) {
                int ks = s2 * 16;
                uint32_t af[4][4], bq[2][4];
#pragma unroll
                for (int mt = 0; mt < 4; mt++) {
                    if (!TA) {
                        int m = wm * 64 + mt * 16 + (lane & 15);
                        int kc = ks + ((lane >> 4) << 3);
                        ldsm4(af[mt], ab2 + (uint32_t)(m * 40 + kc) * 2);
                    } else {
                        int kr = ks + (lane & 7) + ((lane >> 4) << 3);
                        int mc = wm * 64 + mt * 16 + (((lane >> 3) & 1) << 3);
                        ldsm4t(af[mt], ab2 + (uint32_t)(kr * 136 + mc) * 2);
                    }
                }
#pragma unroll
                for (int np = 0; np < 2; np++) {
                    if (TB) {
                        int n = wn * 32 + np * 16 + ((lane >> 4) << 3) + (lane & 7);
                        int kc = ks + (((lane >> 3) & 1) << 3);
                        ldsm4(bq[np], bb2 + (uint32_t)(n * 40 + kc) * 2);
                    } else {
                        int kr = ks + (lane & 7) + (((lane >> 3) & 1) << 3);
                        int nc = wn * 32 + np * 16 + (((lane >> 4) & 1) << 3);
                        ldsm4t(bq[np], bb2 + (uint32_t)(kr * 136 + nc) * 2);
                    }
                }
#pragma unroll
                for (int mt = 0; mt < 4; mt++)
#pragma unroll
                    for (int nt = 0; nt < 4; nt++)
                        mma16816(c[mt][nt], af[mt], &bq[nt >> 1][(nt & 1) * 2]);
            }
        }
        if (kt + 3 < KT) load_stage((kt + 3) & 3, (kt + 3) * 32);
    }

    // ---- fused column-sum epilogue (compare L2): no C store
    if (vacc) {
        int b2v = m0 >> 8;   // 128-row blocks never straddle a 256-row segment
        int voff = (b2v < Bsz) ? b2v * (2 * Hsz) : (b2v - Bsz) * (2 * Hsz) + Hsz;
#pragma unroll
        for (int nt = 0; nt < 4; nt++) {
            int n = n0 + wn * 32 + nt * 8 + tig * 2;
            float s0 = 0.f, s1 = 0.f;
            if (n < N) {
#pragma unroll
                for (int mt = 0; mt < 4; mt++)
#pragma unroll
                    for (int r = 0; r < 2; r++) {
                        int m = m0 + wm * 64 + mt * 16 + g + r * 8;
                        float rsv = rs ? rs[(long)bz * sRS + m] : 1.f;
                        float v0 = c[mt][nt][r * 2 + 0];
                        float v1 = c[mt][nt][r * 2 + 1];
                        if (bias) { v0 += bias[n]; v1 += bias[n + 1]; }
                        if (n < nrelu) { v0 = fmaxf(v0, 0.f); v1 = fmaxf(v1, 0.f); }
                        s0 += v0 * rsv; s1 += v1 * rsv;
                    }
            }
            s0 += __shfl_down_sync(~0u, s0, 16);
            s0 += __shfl_down_sync(~0u, s0, 8);
            s0 += __shfl_down_sync(~0u, s0, 4);
            s1 += __shfl_down_sync(~0u, s1, 16);
            s1 += __shfl_down_sync(~0u, s1, 8);
            s1 += __shfl_down_sync(~0u, s1, 4);
            if (g == 0 && n < N) {
                atomicAdd(&vacc[voff + n], s0);
                atomicAdd(&vacc[voff + n + 1], s1);
            }
        }
        return;
    }

    __half* Ch = (__half*)Cv + (long)bz * sC;
    float*  Cf = (float*)Cv + (long)bz * sC;
#pragma unroll
    for (int mt = 0; mt < 4; mt++) {
#pragma unroll
        for (int r = 0; r < 2; r++) {
            int m = m0 + wm * 64 + mt * 16 + g + r * 8;
            if (m >= M) continue;
            float rsv = rs ? rs[(long)bz * sRS + m] : 1.f;
            int crow = 0;
            if (Cin) crow = iC ? iC[bz * 256 + m] : m;
#pragma unroll
            for (int nt = 0; nt < 4; nt++) {
                int n = n0 + wn * 32 + nt * 8 + tig * 2;
                if (n < N) {
                    float v0 = c[mt][nt][r * 2 + 0];
                    float v1 = c[mt][nt][r * 2 + 1];
                    if (rsPre) { v0 *= rsv; v1 *= rsv; }
                    if (Cin) {
                        v0 += __half2float(Cin[(long)crow * ldcin + n]);
                        v1 += __half2float(Cin[(long)crow * ldcin + n + 1]);
                    }
                    if (bias) { v0 += bias[n]; v1 += bias[n + 1]; }
                    if (n < nrelu) { v0 = fmaxf(v0, 0.f); v1 = fmaxf(v1, 0.f); }
                    if (!rsPre) { v0 *= rsv; v1 *= rsv; }
                    if (OUTH)
                        *(__half2*)(Ch + (long)m * ldc + n) = __floats2half2_rn(v0, v1);
                    else {
                        Cf[(long)m * ldc + n] = v0;
                        Cf[(long)m * ldc + n + 1] = v1;
                    }
                }
            }
        }
    }

    if (bmaxu) {   // per-batch max of this block's outputs (exact tiles only)
        float mx = -1e30f;
#pragma unroll
        for (int mt = 0; mt < 4; mt++)
#pragma unroll
            for (int nt = 0; nt < 4; nt++)
#pragma unroll
                for (int q = 0; q < 4; q++) mx = fmaxf(mx, c[mt][nt][q]);
#pragma unroll
        for (int o = 16; o; o >>= 1) mx = fmaxf(mx, __shfl_xor_sync(~0u, mx, o));
        if (lane == 0) atomicMax(&bmaxu[bz], fenc(mx));
    }
}

// dynamic smem bytes per instantiation (4 stages)
constexpr int smem_bytes(bool TA, bool TB)
{
    int a = TA ? 32 * 136 : 128 * 40;
    int b = TB ? 128 * 40 : 32 * 136;
    return 4 * (a + b) * 2;
}

// ---------------- helper kernels ---------------------------------------------
__global__ void conv2h_k(const float* __restrict__ src, __half* __restrict__ dst,
                         int rows, int cols, int srcR, int srcC)
{
    long idx = (long)blockIdx.x * blockDim.x + threadIdx.x;
    if (idx >= (long)rows * cols) return;
    int r = (int)(idx / cols), c = (int)(idx % cols);
    float v = (r < srcR && c < srcC) ? src[(long)r * srcC + c] : 0.f;
    dst[idx] = __float2half_rn(v);
}

// all weight conversions in ONE kernel (Wcat packing + W2a/W2c/W1g + biascat)
__global__ void convw_k(const float* __restrict__ W1a, const float* __restrict__ W1c,
                        const float* __restrict__ W2a, const float* __restrict__ W2c,
                        const float* __restrict__ W1g, const float* __restrict__ b1a)
{
    long idx = (long)blockIdx.x * blockDim.x + threadIdx.x;
    const long NW = (long)EP * NCAT;
    if (idx < NW) {
        int r = (int)(idx / NCAT), cc = (int)(idx % NCAT);
        float v = 0.f;
        if (r < Esz) {
            if (cc < 200)      v = W1a[(long)r * Hsz + cc];
            else if (cc < 400) v = W1c[(long)r * Hsz + (cc - 200)];
            else if (cc < 600) v = W1c[(long)(Esz + r) * Hsz + (cc - 400)];
        }
        g_Wcat[idx] = __float2half_rn(v);
        return;
    }
    idx -= NW;
    if (idx < Hsz * Hsz) { g_W2a[idx] = __float2half_rn(W2a[idx]); return; }
    idx -= Hsz * Hsz;
    if (idx < Hsz * Hsz) { g_W2c[idx] = __float2half_rn(W2c[idx]); return; }
    idx -= Hsz * Hsz;
    if (idx < 2 * Hsz * Hsz) { g_W1g[idx] = __float2half_rn(W1g[idx]); return; }
    idx -= 2 * Hsz * Hsz;
    if (idx < NCAT) { g_b1acat[idx] = (idx < Hsz) ? b1a[idx] : 0.f; return; }
}

// masks + token index concat + lens + bmax init + vcat accumulator zero
__global__ void mask_k(const int* __restrict__ s1, const int* __restrict__ s2,
                       const int* __restrict__ len1, const int* __restrict__ len2)
{
    long idx = (long)blockIdx.x * blockDim.x + threadIdx.x;
    if (idx >= 2 * BL) return;
    int seq = (int)(idx / BL);
    long r = idx % BL;
    int b = (int)(r / Lsz), l = (int)(r % Lsz);
    int len = seq ? len2[b] : len1[b];
    g_mask[idx] = (l < len) ? 1.f : 0.f;
    g_tok[idx] = seq ? s2[r] : s1[r];
    if (idx < Bsz) g_bmaxu[idx] = 0u;
    if (idx < 2 * Bsz) g_len12[idx] = (idx < Bsz) ? len1[idx] : len2[idx - Bsz];
    if (idx < Bsz * 2 * Hsz) g_vcatf[idx] = 0.f;
}

// Single-pass softmax (shift-cancelled, raw outputs): p = exp(e - Mb);
// write q=p*m1i -> g_eanh, w=p*m2j -> g_ebnh; colsum(q) -> rsa, rowsum(w) -> rsb.
// Normalization moved into th-GEMM epilogues (rsPre row scale).
__global__ void sums_k()
{
    __shared__ float rowacc[256];
    __shared__ float colsm[1024];
    int b = blockIdx.x;
    int tid = threadIdx.x;
    int j = tid & 255, s = tid >> 8, lane = tid & 31;
    if (tid < 256) rowacc[tid] = 0.f;
    __syncthreads();

    long base = (long)b * LL;
    float Mb  = fdec(g_bmaxu[b]);
    float m2j = g_mask[BL + (long)b * Lsz + j];
    float da = 0.f;
    for (int t = 0; t < 64; t++) {
        int i = s * 64 + t;
        long idx = base + (long)i * Lsz + j;
        float p = __expf(g_scores[idx] - Mb);
        float q = p * g_mask[(long)b * Lsz + i];
        da += q;
        g_eanh[idx] = __float2half_rn(q);
        float w = p * m2j;
        g_ebnh[idx] = __float2half_rn(w);
#pragma unroll
        for (int o = 16; o; o >>= 1) w += __shfl_xor_sync(~0u, w, o);
        if (lane == 0) atomicAdd(&rowacc[i], w);
    }
    colsm[tid] = da;
    __syncthreads();
    if (s == 0)
        g_rsa[(long)b * Lsz + j] =
            m2j / (colsm[j] + colsm[j + 256] + colsm[j + 512] + colsm[j + 768]);
    if (tid < 256)
        g_rsb[(long)b * Lsz + tid] = g_mask[(long)b * Lsz + tid] / rowacc[tid];
}

__global__ void vconv_k()    // fp32 vcat accumulator -> fp16
{
    int idx = blockIdx.x * blockDim.x + threadIdx.x;
    if (idx < Bsz * 2 * Hsz) g_vch[idx] = __float2half_rn(g_vcatf[idx]);
}

__global__ void final_k(const float* __restrict__ W2g,
                        const float* __restrict__ b2g, float* __restrict__ out)
{
    int b = blockIdx.x;
    int o = threadIdx.x >> 5;
    int lane = threadIdx.x & 31;
    const float* u = g_u + (long)b * Hsz;
    float s = 0.f;
    for (int h = lane; h < Hsz; h += 32) s += u[h] * W2g[h * 2 + o];
#pragma unroll
    for (int off = 16; off; off >>= 1) s += __shfl_xor_sync(~0u, s, off);
    if (lane == 0) out[b * 2 + o] = s + b2g[o];
}

// ---------------- launch -----------------------------------------------------
extern "C" void kernel_launch(void* const* d_in, const int* in_sizes, int n_in,
                              void* d_out, int out_size)
{
    const float* emb = (const float*)d_in[0];
    const float* W1a = (const float*)d_in[1];
    const float* b1a = (const float*)d_in[2];
    const float* W2a = (const float*)d_in[3];
    const float* b2a = (const float*)d_in[4];
    const float* W1c = (const float*)d_in[5];
    const float* b1c = (const float*)d_in[6];
    const float* W2c = (const float*)d_in[7];
    const float* b2c = (const float*)d_in[8];
    const float* W1g = (const float*)d_in[9];
    const float* b1g = (const float*)d_in[10];
    const float* W2g = (const float*)d_in[11];
    const float* b2g = (const float*)d_in[12];
    const int* s1   = (const int*)d_in[13];
    const int* s2   = (const int*)d_in[14];
    const int* len1 = (const int*)d_in[15];
    const int* len2 = (const int*)d_in[16];
    float* out = (float*)d_out;

    __half *pembh, *pWcat, *pW2a, *pW2c, *pW1g, *pvcb, *phvh;
    __half *peanh, *pebnh, *pthh, *pvch;
    float *pmask, *pu, *psc, *pb1acat, *pvcatf, *prsa, *prsb;
    int *ptok, *plen;
    unsigned *pbmx;
    cudaGetSymbolAddress((void**)&pembh,  g_embh);
    cudaGetSymbolAddress((void**)&pWcat,  g_Wcat);
    cudaGetSymbolAddress((void**)&pW2a,   g_W2a);
    cudaGetSymbolAddress((void**)&pW2c,   g_W2c);
    cudaGetSymbolAddress((void**)&pW1g,   g_W1g);
    cudaGetSymbolAddress((void**)&pvcb,   g_vcb);
    cudaGetSymbolAddress((void**)&phvh,   g_hvh);
    cudaGetSymbolAddress((void**)&peanh,  g_eanh);
    cudaGetSymbolAddress((void**)&pebnh,  g_ebnh);
    cudaGetSymbolAddress((void**)&pthh,   g_thh);
    cudaGetSymbolAddress((void**)&pvch,   g_vch);
    cudaGetSymbolAddress((void**)&pmask,  g_mask);
    cudaGetSymbolAddress((void**)&pu,     g_u);
    cudaGetSymbolAddress((void**)&psc,    g_scores);
    cudaGetSymbolAddress((void**)&pb1acat,g_b1acat);
    cudaGetSymbolAddress((void**)&pvcatf, g_vcatf);
    cudaGetSymbolAddress((void**)&prsa,   g_rsa);
    cudaGetSymbolAddress((void**)&prsb,   g_rsb);
    cudaGetSymbolAddress((void**)&ptok,   g_tok);
    cudaGetSymbolAddress((void**)&plen,   g_len12);
    cudaGetSymbolAddress((void**)&pbmx,   g_bmaxu);

    const int M2 = (int)(2 * BL);          // 262144
    const unsigned MV = (VOC + 127) / 128; // 391
    const int RALL = 1 << 30;              // relu on all columns
    auto cdiv = [](long n, long d) { return (unsigned)((n + d - 1) / d); };

    // KT per call site: EP=304 -> 10, K=200 -> 7, K=256 -> 8, K=400 -> 13
    constexpr int SM_FF = smem_bytes(false, false);   // 75776
    constexpr int SM_FT = smem_bytes(false, true);    // 81920
    constexpr int SM_TF = smem_bytes(true,  false);   // 75776
    cudaFuncSetAttribute((const void*)gemm_h<10,false,false,true>,
                         cudaFuncAttributeMaxDynamicSharedMemorySize, SM_FF);
    cudaFuncSetAttribute((const void*)gemm_h<7,false,false,true>,
                         cudaFuncAttributeMaxDynamicSharedMemorySize, SM_FF);
    cudaFuncSetAttribute((const void*)gemm_h<7,false,true,false>,
                         cudaFuncAttributeMaxDynamicSharedMemorySize, SM_FT);
    cudaFuncSetAttribute((const void*)gemm_h<8,false,false,true>,
                         cudaFuncAttributeMaxDynamicSharedMemorySize, SM_FF);
    cudaFuncSetAttribute((const void*)gemm_h<8,true,false,true>,
                         cudaFuncAttributeMaxDynamicSharedMemorySize, SM_TF);
    cudaFuncSetAttribute((const void*)gemm_h<13,false,false,false>,
                         cudaFuncAttributeMaxDynamicSharedMemorySize, SM_FF);

    // 1. emb -> fp16 (padded)
    conv2h_k<<<cdiv((long)VOC * EP, 256), 256>>>(emb, pembh, VOC, EP, VOC, Esz);
    // 2. all weights in one kernel
    long wtot = (long)EP * NCAT + 2 * Hsz * Hsz + 2 * Hsz * Hsz + NCAT;
    convw_k<<<cdiv(wtot, 256), 256>>>(W1a, W1c, W2a, W2c, W1g, b1a);
    // 3. masks + tok + lens + bmax + vcat zero
    mask_k<<<cdiv(2 * BL, 256), 256>>>(s1, s2, len1, len2);

    // 4. fused vocab GEMM: [attendL1(relu,b1a) | e@W1cT | e@W1cB]  (N=640, K=EP)
    gemm_h<10,false,false,true><<<dim3(5, MV, 1), 256, SM_FF>>>(
        pembh, 0, EP, nullptr, pWcat, 0, NCAT, nullptr, pb1acat, nullptr, 0, 0,
        nullptr, nullptr, 0, pvcb, 0, NCAT, VOC, NCAT, EP, Hsz,
        nullptr, nullptr, nullptr, nullptr, nullptr);
    // 5. attend L2: hv = relu(vcb[:, :200] @ W2a + b2a)   (K=200)
    gemm_h<7,false,false,true><<<dim3(2, MV, 1), 256, SM_FF>>>(
        pvcb, 0, NCAT, nullptr, pW2a, 0, Hsz, nullptr, b2a, nullptr, 0, 0,
        nullptr, nullptr, 0, phvh, 0, Hsz, VOC, Hsz, Hsz, RALL,
        nullptr, nullptr, nullptr, nullptr, nullptr);

    // 6. scores[b] = hv[s1] @ hv[s2]^T (K=200; batch-max; OR-skip masked tiles)
    gemm_h<7,false,true,false><<<dim3(2, 2, Bsz), 256, SM_FT>>>(
        phvh, 0, Hsz, s1, phvh, 0, Hsz, s2, nullptr, nullptr, 0, 0,
        nullptr, nullptr, 0, psc, LL, Lsz, Lsz, Lsz, Hsz, 0,
        pbmx, nullptr, plen, plen + Bsz, nullptr);

    // 7. single-pass softmax -> raw fp16 q/w + rsa/rsb
    sums_k<<<Bsz, 1024>>>();

    // 8. compare hidden: th1[i] = relu(rsb_i*(w_raw@cv2[s2]) + cv[tok] + b1c)
    //    (K=256, k-tiles beyond ceil(len2/32) skipped; row-blocks >= len1 skipped)
    gemm_h<8,false,false,true><<<dim3(2, 2, Bsz), 256, SM_FF>>>(
        pebnh, LL, Lsz, nullptr, pvcb + 400, 0, NCAT, s2, b1c, prsb, Lsz, 1,
        pvcb + 200, ptok, NCAT, pthh, (long)Lsz * Hsz, Hsz,
        Lsz, Hsz, Lsz, RALL, nullptr, nullptr, plen, nullptr, plen + Bsz);
    //    th2[j] = relu(rsa_j*(q_raw^T@cv2[s1]) + cv[tok2] + b1c)
    gemm_h<8,true,false,true><<<dim3(2, 2, Bsz), 256, SM_TF>>>(
        peanh, LL, Lsz, nullptr, pvcb + 400, 0, NCAT, s1, b1c, prsa, Lsz, 1,
        pvcb + 200, ptok + BL, NCAT, pthh + BL * Hsz, (long)Lsz * Hsz, Hsz,
        Lsz, Hsz, Lsz, RALL, nullptr, nullptr, plen + Bsz, nullptr, plen);

    // 9. compare L2 with fused masked column-sum (K=200; skip fully-masked blocks)
    gemm_h<7,false,false,true><<<dim3(2, M2 / 128, 1), 256, SM_FF>>>(
        pthh, 0, Hsz, nullptr, pW2c, 0, Hsz, nullptr, b2c, pmask, 0, 0,
        nullptr, nullptr, 0, nullptr, 0, Hsz, M2, Hsz, Hsz, RALL,
        nullptr, pvcatf, plen, nullptr, nullptr);

    // 10. vcat fp32 -> fp16 ; aggregate head (K=400)
    vconv_k<<<cdiv(Bsz * 2 * Hsz, 256), 256>>>();
    gemm_h<13,false,false,false><<<dim3(2, 4, 1), 256, SM_FF>>>(
        pvch, 0, 2 * Hsz, nullptr, pW1g, 0, Hsz, nullptr, b1g, nullptr, 0, 0,
        nullptr, nullptr, 0, pu, 0, Hsz, Bsz, Hsz, 2 * Hsz, RALL,
        nullptr, nullptr, nullptr, nullptr, nullptr);
    final_k<<<Bsz, 64>>>(W2g, b2g, out);
}